// round 3
// baseline (speedup 1.0000x reference)
#include <cuda_runtime.h>

// Problem constants
#define NT   20    // trees
#define NF   128   // features
#define NN   31    // internal nodes per tree
#define NLF  32    // leaves per tree
#define ROWS 128   // batch rows per block / threads per block
#define XPITCH 132 // padded row stride in shared (floats); 132 mod 32 = 4 -> conflict-free LDS.128

// Scratch (allocation-free, __device__ globals)
__device__ float g_Wm[NT * NN * NF];     // masked split weights
__device__ float g_lcp[NT * NLF * 2];    // leaf class probs (softmaxed)
__device__ float g_tw[NT];               // tree weights (softmaxed)

// ---------------------------------------------------------------------------
// Prep: Wm = split_weights * feature_mask, leaf softmax, tree softmax
// ---------------------------------------------------------------------------
__global__ void prep_kernel(const float* __restrict__ sw,
                            const float* __restrict__ ll,
                            const float* __restrict__ tw,
                            const float* __restrict__ fm)
{
    int idx = blockIdx.x * blockDim.x + threadIdx.x;
    const int total = NT * NN * NF;
    if (idx < total) {
        int f = idx % NF;
        int t = idx / (NN * NF);
        g_Wm[idx] = sw[idx] * fm[t * NF + f];
    }
    if (idx < NT * NLF) {
        float a = ll[2 * idx], b = ll[2 * idx + 1];
        float m  = fmaxf(a, b);
        float e0 = expf(a - m), e1 = expf(b - m);
        float inv = 1.0f / (e0 + e1);
        g_lcp[2 * idx]     = e0 * inv;
        g_lcp[2 * idx + 1] = e1 * inv;
    }
    if (idx == 0) {
        float m = tw[0];
        for (int t = 1; t < NT; ++t) m = fmaxf(m, tw[t]);
        float e[NT];
        float s = 0.0f;
        for (int t = 0; t < NT; ++t) { e[t] = expf(tw[t] - m); s += e[t]; }
        float inv = 1.0f / s;
        for (int t = 0; t < NT; ++t) g_tw[t] = e[t] * inv;
    }
}

// ---------------------------------------------------------------------------
// Main fused kernel: per-thread batch row; per-tree GEMV + sigmoid + path
// product + leaf mix, accumulated over trees. x tile + weight tile in smem.
// ---------------------------------------------------------------------------
__global__ __launch_bounds__(ROWS) void forest_kernel(
    const float* __restrict__ x,
    const float* __restrict__ sbias,
    float* __restrict__ out)
{
    extern __shared__ float smem[];
    float* xs  = smem;                    // ROWS * XPITCH
    float* ws  = xs + ROWS * XPITCH;      // NN * NF
    float* sb  = ws + NN * NF;            // NN
    float* sl  = sb + NN;                 // NLF * 2
    float* stw = sl + NLF * 2;            // NT

    const int tid = threadIdx.x;
    const long long rowBase = (long long)blockIdx.x * ROWS;

    // Load x tile (coalesced float4), store into padded smem rows
    const float4* x4 = reinterpret_cast<const float4*>(x + rowBase * NF);
    #pragma unroll
    for (int i = 0; i < 32; ++i) {        // ROWS*NF/4 / ROWS = 32
        int lin = tid + i * ROWS;
        int r = lin >> 5;                 // / (NF/4)
        int c = lin & 31;                 // % (NF/4)
        float4 v = x4[lin];
        float* d = xs + r * XPITCH + c * 4;
        d[0] = v.x; d[1] = v.y; d[2] = v.z; d[3] = v.w;
    }
    if (tid < NT) stw[tid] = g_tw[tid];

    float o0 = 0.0f, o1 = 0.0f;

    for (int t = 0; t < NT; ++t) {
        __syncthreads();   // protect ws/sb/sl reuse across trees (and first use)
        const float4* w4 = reinterpret_cast<const float4*>(g_Wm + t * NN * NF);
        for (int i = tid; i < NN * NF / 4; i += ROWS)
            reinterpret_cast<float4*>(ws)[i] = w4[i];
        if (tid < NN)      sb[tid] = sbias[t * NN + tid];
        if (tid < NLF * 2) sl[tid] = g_lcp[t * NLF * 2 + tid];
        __syncthreads();

        // 31 dot products of length 128, all accumulators in registers
        float acc[NN];
        #pragma unroll
        for (int n = 0; n < NN; ++n) acc[n] = sb[n];

        const float* xr = xs + tid * XPITCH;
        #pragma unroll 2
        for (int fo = 0; fo < NF; fo += 4) {
            const float x0 = xr[fo + 0], x1 = xr[fo + 1];
            const float x2 = xr[fo + 2], x3 = xr[fo + 3];
            #pragma unroll
            for (int n = 0; n < NN; ++n) {
                const float* wr = ws + n * NF + fo;
                float a = acc[n];
                a = fmaf(x0, wr[0], a);
                a = fmaf(x1, wr[1], a);
                a = fmaf(x2, wr[2], a);
                a = fmaf(x3, wr[3], a);
                acc[n] = a;
            }
        }

        // Sigmoid (fast exp + fast reciprocal; rel err ~2^-21, way under 1e-3)
        #pragma unroll
        for (int n = 0; n < NN; ++n)
            acc[n] = __fdividef(1.0f, 1.0f + __expf(-acc[n]));

        // Level-by-level leaf probability expansion; fully unrolled so P[]
        // stays in registers. Level l nodes occupy indices (2^l - 1) + prefix.
        float P[NLF];
        P[0] = 1.0f;
        #pragma unroll
        for (int lvl = 0; lvl < 5; ++lvl) {
            const int base = (1 << lvl) - 1;
            const int cnt  = 1 << lvl;
            #pragma unroll
            for (int j = cnt - 1; j >= 0; --j) {
                float g  = acc[base + j];
                float pj = P[j];
                P[2 * j + 1] = pj * g;
                P[2 * j]     = fmaf(-pj, g, pj);   // pj * (1 - g)
            }
        }

        // Mix with leaf class probabilities
        float t0 = 0.0f, t1 = 0.0f;
        #pragma unroll
        for (int l = 0; l < NLF; ++l) {
            t0 = fmaf(P[l], sl[2 * l],     t0);
            t1 = fmaf(P[l], sl[2 * l + 1], t1);
        }
        const float w = stw[t];
        o0 = fmaf(w, t0, o0);
        o1 = fmaf(w, t1, o1);
    }

    reinterpret_cast<float2*>(out)[rowBase + tid] = make_float2(o0, o1);
}

// ---------------------------------------------------------------------------
// Launch
// ---------------------------------------------------------------------------
extern "C" void kernel_launch(void* const* d_in, const int* in_sizes, int n_in,
                              void* d_out, int out_size)
{
    const float* x  = (const float*)d_in[0];   // (B, 128)
    const float* sw = (const float*)d_in[1];   // (20, 31, 128)
    const float* sb = (const float*)d_in[2];   // (20, 31)
    const float* ll = (const float*)d_in[3];   // (20, 32, 2)
    const float* tw = (const float*)d_in[4];   // (20,)
    const float* fm = (const float*)d_in[5];   // (20, 128)
    float* out = (float*)d_out;                // (B, 2)

    const int B = in_sizes[0] / NF;

    const size_t shbytes =
        (size_t)(ROWS * XPITCH + NN * NF + NN + NLF * 2 + NT) * sizeof(float);
    cudaFuncSetAttribute(forest_kernel,
                         cudaFuncAttributeMaxDynamicSharedMemorySize,
                         (int)shbytes);

    const int prep_total = NT * NN * NF;
    prep_kernel<<<(prep_total + 255) / 256, 256>>>(sw, ll, tw, fm);
    forest_kernel<<<B / ROWS, ROWS, shbytes>>>(x, sb, out);
}

// round 7
// speedup vs baseline: 3.6825x; 3.6825x over previous
#include <cuda_runtime.h>
#include <cuda_bf16.h>
#include <cstdint>

// ---------------------------------------------------------------------------
// Problem constants
// ---------------------------------------------------------------------------
#define NT   20     // trees
#define NF   128    // features (K)
#define NN   31     // internal nodes (padded to 32 = GEMM N)
#define NLF  32     // leaves
#define ROWS 128    // batch rows per CTA
#define XSTR 136    // padded row stride in bf16 elems (272B = 17 * 16B granules)
#define XSTRB 272   // row stride bytes
#define WH_STRIDE 8704   // bytes between hi and lo W planes in smem (32*272)

// Shared memory layout (bytes)
#define SM_XHI  0
#define SM_XLO  34816
#define SM_W    69632        // [h][32][XSTR] bf16
#define SM_STG  87040        // 4 warps x 32 x 34 floats
#define SM_BIAS 104448       // 32 floats
#define SM_LCP  104576       // 64 floats
#define SM_TOTAL 104832

// ---------------------------------------------------------------------------
// Device scratch (allocation-free)
// ---------------------------------------------------------------------------
__device__ __align__(16) __nv_bfloat16 g_W[NT][2][32][NF];  // [tree][hi/lo][node][feat]
__device__ float g_lcp[NT * NLF * 2];
__device__ float g_tw[NT];

// ---------------------------------------------------------------------------
// Helpers
// ---------------------------------------------------------------------------
__device__ __forceinline__ uint32_t smem_u32(const void* p) {
    uint32_t a;
    asm("{ .reg .u64 t; cvta.to.shared.u64 t, %1; cvt.u32.u64 %0, t; }" : "=r"(a) : "l"(p));
    return a;
}

__device__ __forceinline__ void ldsm4(uint32_t* r, uint32_t addr) {
    asm volatile("ldmatrix.sync.aligned.m8n8.x4.shared.b16 {%0,%1,%2,%3}, [%4];"
                 : "=r"(r[0]), "=r"(r[1]), "=r"(r[2]), "=r"(r[3]) : "r"(addr));
}

__device__ __forceinline__ void mma_bf16(float* c, const uint32_t* a, const uint32_t* b) {
    asm volatile("mma.sync.aligned.m16n8k16.row.col.f32.bf16.bf16.f32 "
                 "{%0,%1,%2,%3}, {%4,%5,%6,%7}, {%8,%9}, {%0,%1,%2,%3};"
                 : "+f"(c[0]), "+f"(c[1]), "+f"(c[2]), "+f"(c[3])
                 : "r"(a[0]), "r"(a[1]), "r"(a[2]), "r"(a[3]), "r"(b[0]), "r"(b[1]));
}

__device__ __forceinline__ float fast_tanh(float x) {
    float r; asm("tanh.approx.f32 %0, %1;" : "=f"(r) : "f"(x)); return r;
}

__device__ __forceinline__ uint32_t pack_bf2(__nv_bfloat16 a, __nv_bfloat16 b) {
    __nv_bfloat162 t(a, b);
    return *reinterpret_cast<uint32_t*>(&t);
}

// ---------------------------------------------------------------------------
// Prep kernel: bf16 hi/lo masked weights, leaf softmax, tree softmax
// ---------------------------------------------------------------------------
__global__ void prep_kernel(const float* __restrict__ sw,
                            const float* __restrict__ ll,
                            const float* __restrict__ tw,
                            const float* __restrict__ fm)
{
    int idx = blockIdx.x * blockDim.x + threadIdx.x;
    const int total = NT * 32 * NF;
    if (idx < total) {
        int t = idx / (32 * NF);
        int r = (idx / NF) & 31;
        int f = idx & (NF - 1);
        float v = 0.0f;
        if (r < NN) v = sw[(t * NN + r) * NF + f] * fm[t * NF + f];
        __nv_bfloat16 hi = __float2bfloat16(v);
        float rem = v - __bfloat162float(hi);
        g_W[t][0][r][f] = hi;
        g_W[t][1][r][f] = __float2bfloat16(rem);
    }
    if (idx < NT * NLF) {
        float a = ll[2 * idx], b = ll[2 * idx + 1];
        float m  = fmaxf(a, b);
        float e0 = expf(a - m), e1 = expf(b - m);
        float inv = 1.0f / (e0 + e1);
        g_lcp[2 * idx]     = e0 * inv;
        g_lcp[2 * idx + 1] = e1 * inv;
    }
    if (idx == 0) {
        float m = tw[0];
        for (int t = 1; t < NT; ++t) m = fmaxf(m, tw[t]);
        float e[NT]; float s = 0.0f;
        for (int t = 0; t < NT; ++t) { e[t] = expf(tw[t] - m); s += e[t]; }
        float inv = 1.0f / s;
        for (int t = 0; t < NT; ++t) g_tw[t] = e[t] * inv;
    }
}

// ---------------------------------------------------------------------------
// Main fused HMMA kernel
// ---------------------------------------------------------------------------
__global__ __launch_bounds__(ROWS, 2) void forest_mma(
    const float* __restrict__ x,
    const float* __restrict__ sbias,
    float* __restrict__ out)
{
    extern __shared__ __align__(16) uint8_t smem[];
    const uint32_t sbase = smem_u32(smem);

    const int tid  = threadIdx.x;
    const int wid  = tid >> 5;
    const int lane = tid & 31;
    const int grp  = lane >> 3;
    const int sub  = lane & 7;

    float* stage = reinterpret_cast<float*>(smem + SM_STG) + wid * 32 * 34;
    float* sBias = reinterpret_cast<float*>(smem + SM_BIAS);
    float* sLcp  = reinterpret_cast<float*>(smem + SM_LCP);

    // ---- Load x tile, convert to bf16 hi/lo, store padded ----
    {
        const float4* x4 = reinterpret_cast<const float4*>(
            x + (size_t)blockIdx.x * ROWS * NF);
        #pragma unroll
        for (int i = 0; i < 32; ++i) {
            int lin = tid + i * ROWS;
            int r  = lin >> 5;          // row
            int c4 = lin & 31;          // float4 index within row
            float4 v = x4[lin];
            __nv_bfloat16 hx = __float2bfloat16(v.x);
            __nv_bfloat16 hy = __float2bfloat16(v.y);
            __nv_bfloat16 hz = __float2bfloat16(v.z);
            __nv_bfloat16 hw = __float2bfloat16(v.w);
            uint32_t* dh = reinterpret_cast<uint32_t*>(smem + SM_XHI + r * XSTRB + c4 * 8);
            uint32_t* dl = reinterpret_cast<uint32_t*>(smem + SM_XLO + r * XSTRB + c4 * 8);
            dh[0] = pack_bf2(hx, hy);
            dh[1] = pack_bf2(hz, hw);
            dl[0] = pack_bf2(__float2bfloat16(v.x - __bfloat162float(hx)),
                             __float2bfloat16(v.y - __bfloat162float(hy)));
            dl[1] = pack_bf2(__float2bfloat16(v.z - __bfloat162float(hz)),
                             __float2bfloat16(v.w - __bfloat162float(hw)));
        }
    }

    // ---- Load tree 0's W/bias/lcp into smem ----
    {
        const float4* src = reinterpret_cast<const float4*>(&g_W[0][0][0][0]);
        #pragma unroll
        for (int j = 0; j < 8; ++j) {
            int idx = tid + j * ROWS;            // float4 index, 1024 total
            int h   = idx >> 9;
            int rem = idx & 511;
            int n   = rem >> 4;
            int k8  = rem & 15;
            float4 v = src[idx];
            *reinterpret_cast<float4*>(smem + SM_W + h * WH_STRIDE + n * XSTRB + k8 * 16) = v;
        }
        if (tid < NN)      sBias[tid] = sbias[tid];
        if (tid < NLF * 2) sLcp[tid]  = g_lcp[tid] * g_tw[0];
    }
    __syncthreads();

    // ---- Per-lane ldmatrix base addresses ----
    // A: groups (m0k0),(m8k0),(m0k8),(m8k8)
    const int aRow  = ((grp & 1) << 3) + sub;
    const int aCol  = (grp >> 1) << 4;          // bytes
    const int warpM = wid << 5;
    const uint32_t aHi0 = sbase + SM_XHI + (warpM +      aRow) * XSTRB + aCol;
    const uint32_t aHi1 = aHi0 + 16 * XSTRB;
    const uint32_t aLo0 = aHi0 + (SM_XLO - SM_XHI);
    const uint32_t aLo1 = aHi1 + (SM_XLO - SM_XHI);
    // B: groups (n0 k0),(n0 k8),(n8 k0),(n8 k8)
    const int bRow = ((grp >> 1) << 3) + sub;
    const int bCol = (grp & 1) << 4;            // bytes
    const uint32_t bHi0 = sbase + SM_W + (bRow)      * XSTRB + bCol;   // n-tiles 0,1
    const uint32_t bHi1 = sbase + SM_W + (bRow + 16) * XSTRB + bCol;   // n-tiles 2,3
    const uint32_t bLo0 = bHi0 + WH_STRIDE;
    const uint32_t bLo1 = bHi1 + WH_STRIDE;

    float o0 = 0.0f, o1 = 0.0f;

    for (int t = 0; t < NT; ++t) {
        // -- Prefetch next tree's W/bias/lcp into registers (overlaps K loop) --
        float4 pw[8];
        float  pb = 0.0f, pl = 0.0f;
        if (t + 1 < NT) {
            const float4* src = reinterpret_cast<const float4*>(&g_W[t + 1][0][0][0]);
            #pragma unroll
            for (int j = 0; j < 8; ++j) pw[j] = src[tid + j * ROWS];
            if (tid < NN)      pb = sbias[(t + 1) * NN + tid];
            if (tid < NLF * 2) pl = g_lcp[(t + 1) * NLF * 2 + tid] * g_tw[t + 1];
        }

        // -- K loop: 8 k16 steps, 3-term bf16 MMA --
        float acc[2][4][4];
        #pragma unroll
        for (int m = 0; m < 2; ++m)
            #pragma unroll
            for (int n = 0; n < 4; ++n)
                #pragma unroll
                for (int i = 0; i < 4; ++i) acc[m][n][i] = 0.0f;

        #pragma unroll
        for (int k = 0; k < 8; ++k) {
            const uint32_t ko = k * 32;
            uint32_t ah0[4], ah1[4], al0[4], al1[4];
            uint32_t bh0[4], bh1[4], bl0[4], bl1[4];
            ldsm4(ah0, aHi0 + ko); ldsm4(ah1, aHi1 + ko);
            ldsm4(al0, aLo0 + ko); ldsm4(al1, aLo1 + ko);
            ldsm4(bh0, bHi0 + ko); ldsm4(bh1, bHi1 + ko);
            ldsm4(bl0, bLo0 + ko); ldsm4(bl1, bLo1 + ko);

            // hi * hi
            mma_bf16(acc[0][0], ah0, bh0);     mma_bf16(acc[0][1], ah0, bh0 + 2);
            mma_bf16(acc[0][2], ah0, bh1);     mma_bf16(acc[0][3], ah0, bh1 + 2);
            mma_bf16(acc[1][0], ah1, bh0);     mma_bf16(acc[1][1], ah1, bh0 + 2);
            mma_bf16(acc[1][2], ah1, bh1);     mma_bf16(acc[1][3], ah1, bh1 + 2);
            // hi * lo
            mma_bf16(acc[0][0], ah0, bl0);     mma_bf16(acc[0][1], ah0, bl0 + 2);
            mma_bf16(acc[0][2], ah0, bl1);     mma_bf16(acc[0][3], ah0, bl1 + 2);
            mma_bf16(acc[1][0], ah1, bl0);     mma_bf16(acc[1][1], ah1, bl0 + 2);
            mma_bf16(acc[1][2], ah1, bl1);     mma_bf16(acc[1][3], ah1, bl1 + 2);
            // lo * hi
            mma_bf16(acc[0][0], al0, bh0);     mma_bf16(acc[0][1], al0, bh0 + 2);
            mma_bf16(acc[0][2], al0, bh1);     mma_bf16(acc[0][3], al0, bh1 + 2);
            mma_bf16(acc[1][0], al1, bh0);     mma_bf16(acc[1][1], al1, bh0 + 2);
            mma_bf16(acc[1][2], al1, bh1);     mma_bf16(acc[1][3], al1, bh1 + 2);
        }

        // -- Transpose logits through per-warp staging buffer --
        {
            const int r0 = lane >> 2;          // row within m-tile
            const int cb = (lane & 3) << 1;    // col base within n-tile
            #pragma unroll
            for (int m = 0; m < 2; ++m)
                #pragma unroll
                for (int n = 0; n < 4; ++n) {
                    const int col = n * 8 + cb;
                    float2* p0 = reinterpret_cast<float2*>(&stage[(m * 16 + r0)     * 34 + col]);
                    float2* p1 = reinterpret_cast<float2*>(&stage[(m * 16 + r0 + 8) * 34 + col]);
                    *p0 = make_float2(acc[m][n][0], acc[m][n][1]);
                    *p1 = make_float2(acc[m][n][2], acc[m][n][3]);
                }
        }
        __syncwarp();

        // -- Epilogue: lane owns one full row --
        {
            float g[NN];
            const float* row = &stage[lane * 34];
            #pragma unroll
            for (int n = 0; n < NN; ++n) {
                float lg = row[n] + sBias[n];
                g[n] = fmaf(fast_tanh(0.5f * lg), 0.5f, 0.5f);   // sigmoid
            }
            float P[NLF];
            P[0] = 1.0f;
            #pragma unroll
            for (int lvl = 0; lvl < 5; ++lvl) {
                const int base = (1 << lvl) - 1;
                const int cnt  = 1 << lvl;
                #pragma unroll
                for (int j = cnt - 1; j >= 0; --j) {
                    float gg = g[base + j];
                    float pj = P[j];
                    P[2 * j + 1] = pj * gg;
                    P[2 * j]     = fmaf(-pj, gg, pj);
                }
            }
            float t0 = 0.0f, t1 = 0.0f;
            #pragma unroll
            for (int l = 0; l < NLF; ++l) {
                t0 = fmaf(P[l], sLcp[2 * l],     t0);
                t1 = fmaf(P[l], sLcp[2 * l + 1], t1);
            }
            o0 += t0; o1 += t1;
        }
        __syncwarp();   // stage reuse next tree

        // -- Swap in prefetched tree (W single-buffered: full barrier) --
        if (t + 1 < NT) {
            __syncthreads();
            #pragma unroll
            for (int j = 0; j < 8; ++j) {
                int idx = tid + j * ROWS;
                int h   = idx >> 9;
                int rem = idx & 511;
                int n   = rem >> 4;
                int k8  = rem & 15;
                *reinterpret_cast<float4*>(smem + SM_W + h * WH_STRIDE + n * XSTRB + k8 * 16) = pw[j];
            }
            if (tid < NN)      sBias[tid] = pb;
            if (tid < NLF * 2) sLcp[tid]  = pl;
            __syncthreads();
        }
    }

    // warp w, lane l owns global row blockIdx*128 + w*32 + l
    const size_t orow = (size_t)blockIdx.x * ROWS + warpM + lane;
    reinterpret_cast<float2*>(out)[orow] = make_float2(o0, o1);
}

// ---------------------------------------------------------------------------
// Launch
// ---------------------------------------------------------------------------
extern "C" void kernel_launch(void* const* d_in, const int* in_sizes, int n_in,
                              void* d_out, int out_size)
{
    const float* x  = (const float*)d_in[0];   // (B, 128)
    const float* sw = (const float*)d_in[1];   // (20, 31, 128)
    const float* sb = (const float*)d_in[2];   // (20, 31)
    const float* ll = (const float*)d_in[3];   // (20, 32, 2)
    const float* tw = (const float*)d_in[4];   // (20,)
    const float* fm = (const float*)d_in[5];   // (20, 128)
    float* out = (float*)d_out;                // (B, 2)

    const int B = in_sizes[0] / NF;

    cudaFuncSetAttribute(forest_mma,
                         cudaFuncAttributeMaxDynamicSharedMemorySize, SM_TOTAL);

    const int prep_total = NT * 32 * NF;
    prep_kernel<<<(prep_total + 255) / 256, 256>>>(sw, ll, tw, fm);
    forest_mma<<<B / ROWS, ROWS, SM_TOTAL>>>(x, sb, out);
}